// round 16
// baseline (speedup 1.0000x reference)
#include <cuda_runtime.h>

#define DD 64
#define FF 8
#define ZZ 72          // D + F
#define HH 256
#define TT 50
#define TUU 128
#define CTAS 148
#define NT 512

typedef unsigned long long u64;

__device__ __forceinline__ u64 fma2(u64 a, u64 b, u64 c) {
    u64 d;
    asm("fma.rn.f32x2 %0, %1, %2, %3;" : "=l"(d) : "l"(a), "l"(b), "l"(c));
    return d;
}
__device__ __forceinline__ u64 add2(u64 a, u64 b) {
    u64 d;
    asm("add.rn.f32x2 %0, %1, %2;" : "=l"(d) : "l"(a), "l"(b));
    return d;
}
__device__ __forceinline__ u64 pack2(float lo, float hi) {
    u64 d;
    asm("mov.b64 %0, {%1, %2};" : "=l"(d) : "f"(lo), "f"(hi));
    return d;
}
__device__ __forceinline__ float2 unpack2(u64 v) {
    float lo, hi;
    asm("mov.b64 {%0, %1}, %2;" : "=f"(lo), "=f"(hi) : "l"(v));
    return make_float2(lo, hi);
}
// a * (s,s) + c, packed
__device__ __forceinline__ u64 fma2s(u64 a, float s, u64 c) {
    return fma2(a, pack2(s, s), c);
}
// Single-MUFU tanh (sm_75+). rel err ~6e-4, damped through integrator.
__device__ __forceinline__ float fast_tanh(float x) {
    float r;
    asm("tanh.approx.f32 %0, %1;" : "=f"(r) : "f"(x));
    return r;
}

// Named barriers: 1+G z-ready (512), 3+G h-ready (512), 5 L1-int (256), 6 L2-int (256)
#define BSYNC(id, cnt) asm volatile("bar.sync %0, %1;"   :: "r"(id), "n"(cnt) : "memory")
#define BARV(id, cnt)  asm volatile("bar.arrive %0, %1;" :: "r"(id), "n"(cnt) : "memory")

// SMEM floats: ubuf 7168 | zbuf 576 | hbuf 2048 | p1 1024 | p2 2*2048=4096 | te 64 | tu 128
#define SMEM_FLOATS (7168 + 576 + 2048 + 1024 + 4096 + 64 + 128)
#define OFF_TE (7168 + 576 + 2048 + 1024 + 4096)

// exact jnp.searchsorted(side='right')-1 semantics
__device__ __forceinline__ void u_interp(float* zG, const float* tu,
                                         const float* ub, int gbase, int i2,
                                         float tst) {
    int r = i2 >> 3, f = i2 & 7;
    int idx = (int)floorf(tst * (float)(TUU - 1));
    idx = max(0, min(TUU - 2, idx));
    while (idx > 0 && tu[idx] > tst) --idx;
    while (idx < TUU - 2 && tu[idx + 1] <= tst) ++idx;
    float t0 = tu[idx], t1 = tu[idx + 1];
    float w = (tst - t0) / (t1 - t0);
    const float* ur = ub + (gbase + r) * (TUU * FF);
    float u0 = ur[idx * FF + f], u1 = ur[(idx + 1) * FF + f];
    zG[r * ZZ + DD + f] = u0 + w * (u1 - u0);
}

// ============ specialized worker body: G0N rows in group0, 3 in group1 ============
template <int G0N>
__device__ __forceinline__ void run_cta(
    float* sm, int tid, int b0,
    const float* __restrict__ x0g, const float* __restrict__ W1g,
    const float* __restrict__ b1g, const float* __restrict__ W2g,
    const float* __restrict__ b2g, float* __restrict__ out)
{
    float* ubuf = sm;                  // [G0N+3][TUU][FF]
    float* zbuf = ubuf + 7168;         // [2][4][ZZ]
    float* hbuf = zbuf + 576;          // [2][4][HH]
    float* p1   = hbuf + 2048;         // [4][128] u64 -> 1024 floats
    float* p2   = p1 + 1024;           // [2G][4][8][64] (double-buffered by G)
    float* te   = p2 + 4096;           // [64]
    float* tu   = te + 64;             // [TUU]
    u64* hq  = reinterpret_cast<u64*>(hbuf);
    u64* p1q = reinterpret_cast<u64*>(p1);
    u64* p2q = reinterpret_cast<u64*>(p2);

    // Dopri5 tableau (fp32-rounded)
    const float A21 = 0.2f;
    const float A31 = 0.075f,                    A32 = 0.225f;
    const float A41 = (float)( 44.0/45.0),       A42 = (float)(-56.0/15.0),
                A43 = (float)( 32.0/9.0);
    const float A51 = (float)( 19372.0/6561.0),  A52 = (float)(-25360.0/2187.0),
                A53 = (float)( 64448.0/6561.0),  A54 = (float)(-212.0/729.0);
    const float A61 = (float)( 9017.0/3168.0),   A62 = (float)(-355.0/33.0),
                A63 = (float)( 46732.0/5247.0),  A64 = (float)( 49.0/176.0),
                A65 = (float)(-5103.0/18656.0);
    const float B1  = (float)( 35.0/384.0),      B3  = (float)(500.0/1113.0),
                B4  = (float)(125.0/192.0),      B5  = (float)(-2187.0/6784.0),
                B6  = (float)( 11.0/84.0);

    if (tid < 256) {
        // ---------------- LAYER-1 WORKERS (warps 0-7), unchanged R15 ----------------
        const int half = tid >> 7;
        const int t    = tid & 127;
        const int j0   = 2 * t;
        u64 w1a[18], w1b[18];
#pragma unroll
        for (int i = 0; i < 18; ++i) {
            int k = half * 36 + 2 * i;
            w1a[i] = pack2(W1g[k * HH + j0],     W1g[(k + 1) * HH + j0]);
            w1b[i] = pack2(W1g[k * HH + j0 + 1], W1g[(k + 1) * HH + j0 + 1]);
        }
        const float b10 = b1g[j0], b11 = b1g[j0 + 1];

        __syncthreads();               // init complete

        for (int it = 0; it < 196 * 6; ++it) {
#pragma unroll
            for (int G = 0; G < 2; ++G) {
                const int nr = (G == 0) ? G0N : 3;
                BSYNC(1 + G, 512);                 // wait z(G) ready
                const float* zb = zbuf + G * 288 + half * 36;
                float pr0[4], pr1[4];
#pragma unroll
                for (int r = 0; r < 4; ++r) {
                    if (r < nr) {
                        const ulonglong2* zr =
                            reinterpret_cast<const ulonglong2*>(zb + r * ZZ);
                        u64 a0 = 0ull, a1 = 0ull, c0 = 0ull, c1 = 0ull;
#pragma unroll
                        for (int i = 0; i < 9; ++i) {  // 9 LDS.128, 36 FMA2
                            ulonglong2 zz = zr[i];
                            a0 = fma2(zz.x, w1a[2 * i],     a0);
                            a1 = fma2(zz.y, w1a[2 * i + 1], a1);
                            c0 = fma2(zz.x, w1b[2 * i],     c0);
                            c1 = fma2(zz.y, w1b[2 * i + 1], c1);
                        }
                        float2 fa = unpack2(a0), fb = unpack2(a1);
                        float2 fc = unpack2(c0), fd = unpack2(c1);
                        pr0[r] = (fa.x + fa.y) + (fb.x + fb.y);
                        pr1[r] = (fc.x + fc.y) + (fd.x + fd.y);
                    }
                }
                if (half == 0) {
                    p1q[2 * 128 + t] = pack2(pr0[2], pr1[2]);
                    if (nr > 3)
                        p1q[3 * 128 + t] = pack2(pr0[3], pr1[3]);
                    BSYNC(5, 256);                 // L1-internal
                    {
                        float2 pp = unpack2(p1q[0 * 128 + t]);
                        hq[G * 512 + 0 * 128 + t] =
                            pack2(fast_tanh(pr0[0] + pp.x + b10),
                                  fast_tanh(pr1[0] + pp.y + b11));
                    }
                    {
                        float2 pp = unpack2(p1q[1 * 128 + t]);
                        hq[G * 512 + 1 * 128 + t] =
                            pack2(fast_tanh(pr0[1] + pp.x + b10),
                                  fast_tanh(pr1[1] + pp.y + b11));
                    }
                } else {
                    p1q[0 * 128 + t] = pack2(pr0[0], pr1[0]);
                    p1q[1 * 128 + t] = pack2(pr0[1], pr1[1]);
                    BSYNC(5, 256);                 // L1-internal
                    {
                        float2 pp = unpack2(p1q[2 * 128 + t]);
                        hq[G * 512 + 2 * 128 + t] =
                            pack2(fast_tanh(pr0[2] + pp.x + b10),
                                  fast_tanh(pr1[2] + pp.y + b11));
                    }
                    if (nr > 3) {
                        float2 pp = unpack2(p1q[3 * 128 + t]);
                        hq[G * 512 + 3 * 128 + t] =
                            pack2(fast_tanh(pr0[3] + pp.x + b10),
                                  fast_tanh(pr1[3] + pp.y + b11));
                    }
                }
                BARV(3 + G, 512);                  // h(G) ready
            }
        }
    } else {
        // ---------------- LAYER-2 WORKERS (warps 8-15) ----------------
        // dot: thread (pg, dp) cols (2dp, 2dp+1), K-slice [pg*32,+32).
        // OWNERSHIP (new): warp pg<4 owns row er=pg, column PAIR (2dp, 2dp+1),
        // state packed f32x2. Warps 4-7 skip the reduce/tableau tail.
        const int i2 = tid - 256;
        const int pg = i2 >> 5;
        const int dp = i2 & 31;
        const int c0 = 2 * dp;
        u64 w2a[16], w2b[16];
#pragma unroll
        for (int i = 0; i < 16; ++i) {
            int k = pg * 32 + 2 * i;
            w2a[i] = pack2(W2g[k * DD + c0],     W2g[(k + 1) * DD + c0]);
            w2b[i] = pack2(W2g[k * DD + c0 + 1], W2g[(k + 1) * DD + c0 + 1]);
        }
        const u64 b2p = pack2(b2g[c0], b2g[c0 + 1]);
        const bool own0 = (pg < G0N);      // G0 owner (row pg)
        const bool own1 = (pg < 3);        // G1 owner
        u64 xc2[2], kk2[2][6];
#pragma unroll
        for (int G = 0; G < 2; ++G) {
            const bool own = G ? own1 : own0;
            if (own) {
                size_t grow = (size_t)(b0 + (G ? G0N : 0) + pg);
                xc2[G] = *reinterpret_cast<const u64*>(x0g + grow * DD + c0);
                *reinterpret_cast<u64*>(out + grow * (TT * DD) + c0) = xc2[G];
            }
        }

        __syncthreads();               // init complete

        // prologue: z for stage 0 of substep 0 (x-part + u-part), both groups
#pragma unroll
        for (int G = 0; G < 2; ++G) {
            const int nr = (G == 0) ? G0N : 3;
            const bool own = G ? own1 : own0;
            if (own)
                *reinterpret_cast<u64*>(zbuf + G * 288 + pg * ZZ + c0) = xc2[G];
            if (i2 < nr * 8)
                u_interp(zbuf + G * 288, tu, ubuf, G ? G0N : 0, i2, te[0]);
            BARV(1 + G, 512);
        }

        for (int m = 0; m < 196; ++m) {
            const int ci = m >> 2, s = m & 3;
            const float tc0 = te[ci];
            const float dtc = te[ci + 1] - tc0;
            const float dt  = dtc * 0.25f;
            const float tsub = tc0 + dtc * ((float)s * 0.25f);
#pragma unroll
            for (int st = 0; st < 6; ++st) {
#pragma unroll
                for (int G = 0; G < 2; ++G) {
                    const int nr = (G == 0) ? G0N : 3;
                    const bool own = G ? own1 : own0;
                    BSYNC(3 + G, 512);             // wait h(G)
                    float* zG = zbuf + G * 288;
                    const bool last = (m == 195) && (st == 5);

                    // HOISTED u-part of NEXT z(G) (overlaps dot)
                    if (i2 < nr * 8 && !last) {
                        const float CSTN[5] = {0.2f, 0.3f, 0.8f,
                                               (float)(8.0/9.0), 1.0f};
                        float tnext = (st < 5)
                            ? tsub + CSTN[st] * dt
                            : ((s < 3) ? tc0 + dtc * ((float)(s + 1) * 0.25f)
                                       : te[ci + 1]);
                        u_interp(zG, tu, ubuf, G ? G0N : 0, i2, tnext);
                    }

                    // xs partial-precompute (all kk up to st-1 known; overlaps dot)
                    u64 xp = 0ull;
                    float aLast;
                    if (own) {
                        switch (st) {
                        case 0: xp = xc2[G]; aLast = A21; break;
                        case 1: xp = fma2s(kk2[G][0], dt * A31, xc2[G]);
                                aLast = A32; break;
                        case 2: xp = fma2s(kk2[G][1], dt * A42,
                                    fma2s(kk2[G][0], dt * A41, xc2[G]));
                                aLast = A43; break;
                        case 3: xp = fma2s(kk2[G][2], dt * A53,
                                    fma2s(kk2[G][1], dt * A52,
                                    fma2s(kk2[G][0], dt * A51, xc2[G])));
                                aLast = A54; break;
                        case 4: xp = fma2s(kk2[G][3], dt * A64,
                                    fma2s(kk2[G][2], dt * A63,
                                    fma2s(kk2[G][1], dt * A62,
                                    fma2s(kk2[G][0], dt * A61, xc2[G]))));
                                aLast = A65; break;
                        default: xp = fma2s(kk2[G][4], dt * B5,
                                     fma2s(kk2[G][3], dt * B4,
                                     fma2s(kk2[G][2], dt * B3,
                                     fma2s(kk2[G][0], dt * B1, xc2[G]))));
                                aLast = B6; break;
                        }
                    }

                    const float* hb = hbuf + G * 1024 + pg * 32;
                    u64* p2g = p2q + G * 1024;
#pragma unroll
                    for (int r = 0; r < 4; ++r) {
                        if (r < nr) {
                            const ulonglong2* hr =
                                reinterpret_cast<const ulonglong2*>(hb + r * HH);
                            u64 a0 = 0ull, a1 = 0ull, d0 = 0ull, d1 = 0ull;
#pragma unroll
                            for (int i = 0; i < 8; ++i) {  // 8 LDS.128, 32 FMA2
                                ulonglong2 hh = hr[i];
                                a0 = fma2(hh.x, w2a[2 * i],     a0);
                                a1 = fma2(hh.y, w2a[2 * i + 1], a1);
                                d0 = fma2(hh.x, w2b[2 * i],     d0);
                                d1 = fma2(hh.y, w2b[2 * i + 1], d1);
                            }
                            float2 fa = unpack2(a0), fb = unpack2(a1);
                            float2 fc = unpack2(d0), fd = unpack2(d1);
                            p2g[r * 256 + i2] =
                                pack2((fa.x + fa.y) + (fb.x + fb.y),
                                      (fc.x + fc.y) + (fd.x + fd.y));
                        }
                    }
                    BSYNC(6, 256);                 // L2-internal
                    if (own) {
                        // paired-column reduce: 8 u64 loads, tree sum
                        const u64* pe = p2g + pg * 256 + dp;
                        u64 q0 = pe[0],       q1 = pe[32],
                            q2 = pe[64],      q3 = pe[96],
                            q4 = pe[128],     q5 = pe[160],
                            q6 = pe[192],     q7 = pe[224];
                        u64 kv2 = add2(add2(add2(q0, q1), add2(q2, q3)),
                                       add2(add2(q4, q5), add2(q6, q7)));
                        kv2 = add2(kv2, b2p);
                        kk2[G][st] = kv2;
                        u64 xs = fma2s(kv2, dt * aLast, xp);
                        if (st < 5) {
                            *reinterpret_cast<u64*>(zG + pg * ZZ + c0) = xs;
                        } else {
                            xc2[G] = xs;
                            if (s == 3) {
                                size_t grow = (size_t)(b0 + (G ? G0N : 0) + pg);
                                *reinterpret_cast<u64*>(
                                    out + grow * (TT * DD) + (ci + 1) * DD + c0) = xs;
                            }
                            if (!last)
                                *reinterpret_cast<u64*>(zG + pg * ZZ + c0) = xs;
                        }
                    }
                    if (!last) BARV(1 + G, 512);   // z(G) ready
                }
            }
        }
    }
}

__global__ void __launch_bounds__(NT, 1)
node_kernel(const float* __restrict__ x0g, const float* __restrict__ te_g,
            const float* __restrict__ tu_g, const float* __restrict__ u_g,
            const float* __restrict__ W1g, const float* __restrict__ b1g,
            const float* __restrict__ W2g, const float* __restrict__ b2g,
            float* __restrict__ out)
{
    extern __shared__ float sm[];
    const int tid = threadIdx.x;
    const int cta = blockIdx.x;
    // 136 CTAs x 7 rows + 12 CTAs x 6 rows = 1024
    const int NR  = (cta < 136) ? 7 : 6;
    const int b0  = (cta < 136) ? cta * 7 : 952 + (cta - 136) * 6;

    // one-time smem loads (common)
    float* te = sm + OFF_TE;
    float* tu = te + 64;
    for (int i = tid; i < TT;  i += NT) te[i] = te_g[i];
    for (int i = tid; i < TUU; i += NT) tu[i] = tu_g[i];
    for (int i = tid; i < NR * TUU * FF; i += NT) {
        int r = i / (TUU * FF);
        int o = i - r * (TUU * FF);
        sm[i] = u_g[(size_t)(b0 + r) * (TUU * FF) + o];
    }

    if (cta < 136)
        run_cta<4>(sm, tid, b0, x0g, W1g, b1g, W2g, b2g, out);
    else
        run_cta<3>(sm, tid, b0, x0g, W1g, b1g, W2g, b2g, out);
}

extern "C" void kernel_launch(void* const* d_in, const int* in_sizes, int n_in,
                              void* d_out, int out_size) {
    const float* x0 = (const float*)d_in[0];
    const float* te = (const float*)d_in[1];
    const float* tu = (const float*)d_in[2];
    const float* ub = (const float*)d_in[3];
    const float* W1 = (const float*)d_in[4];
    const float* b1 = (const float*)d_in[5];
    const float* W2 = (const float*)d_in[6];
    const float* b2 = (const float*)d_in[7];
    float* out = (float*)d_out;

    const int smem_bytes = SMEM_FLOATS * (int)sizeof(float);   // 60416 B
    cudaFuncSetAttribute(node_kernel,
                         cudaFuncAttributeMaxDynamicSharedMemorySize, smem_bytes);
    node_kernel<<<CTAS, NT, smem_bytes>>>(x0, te, tu, ub, W1, b1, W2, b2, out);
}

// round 17
// speedup vs baseline: 1.1817x; 1.1817x over previous
#include <cuda_runtime.h>

#define DD 64
#define FF 8
#define ZZ 72          // D + F
#define HH 256
#define TT 50
#define TUU 128
#define CTAS 148
#define NT 512

typedef unsigned long long u64;

__device__ __forceinline__ u64 fma2(u64 a, u64 b, u64 c) {
    u64 d;
    asm("fma.rn.f32x2 %0, %1, %2, %3;" : "=l"(d) : "l"(a), "l"(b), "l"(c));
    return d;
}
__device__ __forceinline__ u64 pack2(float lo, float hi) {
    u64 d;
    asm("mov.b64 %0, {%1, %2};" : "=l"(d) : "f"(lo), "f"(hi));
    return d;
}
__device__ __forceinline__ float2 unpack2(u64 v) {
    float lo, hi;
    asm("mov.b64 {%0, %1}, %2;" : "=f"(lo), "=f"(hi) : "l"(v));
    return make_float2(lo, hi);
}
// Single-MUFU tanh (sm_75+). rel err ~6e-4, damped ~0.07x through integrator.
__device__ __forceinline__ float fast_tanh(float x) {
    float r;
    asm("tanh.approx.f32 %0, %1;" : "=f"(r) : "f"(x));
    return r;
}

// Named barriers: 1+G z-ready (512), 3+G h-ready (512), 5 L1-int (256), 6 L2-int (256)
#define BSYNC(id, cnt) asm volatile("bar.sync %0, %1;"   :: "r"(id), "n"(cnt) : "memory")
#define BARV(id, cnt)  asm volatile("bar.arrive %0, %1;" :: "r"(id), "n"(cnt) : "memory")

// SMEM floats: ubuf 7168 | zbuf 576 | hbuf 2048 | p1 1024 | p2 2*2048=4096 | te 64 | tu 128
#define SMEM_FLOATS (7168 + 576 + 2048 + 1024 + 4096 + 64 + 128)
#define OFF_TE (7168 + 576 + 2048 + 1024 + 4096)

// exact jnp.searchsorted(side='right')-1 semantics
__device__ __forceinline__ void u_interp(float* zG, const float* tu,
                                         const float* ub, int gbase, int i2,
                                         float tst) {
    int r = i2 >> 3, f = i2 & 7;
    int idx = (int)floorf(tst * (float)(TUU - 1));
    idx = max(0, min(TUU - 2, idx));
    while (idx > 0 && tu[idx] > tst) --idx;
    while (idx < TUU - 2 && tu[idx + 1] <= tst) ++idx;
    float t0 = tu[idx], t1 = tu[idx + 1];
    float w = (tst - t0) / (t1 - t0);
    const float* ur = ub + (gbase + r) * (TUU * FF);
    float u0 = ur[idx * FF + f], u1 = ur[(idx + 1) * FF + f];
    zG[r * ZZ + DD + f] = u0 + w * (u1 - u0);
}

// ============ specialized worker body: G0N rows in group0, 3 in group1 ============
template <int G0N>
__device__ __forceinline__ void run_cta(
    float* sm, int tid, int b0,
    const float* __restrict__ x0g, const float* __restrict__ W1g,
    const float* __restrict__ b1g, const float* __restrict__ W2g,
    const float* __restrict__ b2g, float* __restrict__ out)
{
    float* ubuf = sm;                  // [G0N+3][TUU][FF]
    float* zbuf = ubuf + 7168;         // [2][4][ZZ]
    float* hbuf = zbuf + 576;          // [2][4][HH]
    float* p1   = hbuf + 2048;         // [4][128] u64 -> 1024 floats
    float* p2   = p1 + 1024;           // [2G][4][8][64] (double-buffered by G)
    float* te   = p2 + 4096;           // [64]
    float* tu   = te + 64;             // [TUU]
    u64* hq  = reinterpret_cast<u64*>(hbuf);
    u64* p1q = reinterpret_cast<u64*>(p1);
    u64* p2q = reinterpret_cast<u64*>(p2);

    // Dopri5 tableau (fp32-rounded)
    const float A21 = 0.2f;
    const float A31 = 0.075f,                    A32 = 0.225f;
    const float A41 = (float)( 44.0/45.0),       A42 = (float)(-56.0/15.0),
                A43 = (float)( 32.0/9.0);
    const float A51 = (float)( 19372.0/6561.0),  A52 = (float)(-25360.0/2187.0),
                A53 = (float)( 64448.0/6561.0),  A54 = (float)(-212.0/729.0);
    const float A61 = (float)( 9017.0/3168.0),   A62 = (float)(-355.0/33.0),
                A63 = (float)( 46732.0/5247.0),  A64 = (float)( 49.0/176.0),
                A65 = (float)(-5103.0/18656.0);
    const float B1  = (float)( 35.0/384.0),      B3  = (float)(500.0/1113.0),
                B4  = (float)(125.0/192.0),      B5  = (float)(-2187.0/6784.0),
                B6  = (float)( 11.0/84.0);

    if (tid < 256) {
        // ---------------- LAYER-1 WORKERS (warps 0-7) ----------------
        const int half = tid >> 7;
        const int t    = tid & 127;
        const int j0   = 2 * t;
        u64 w1a[18], w1b[18];
#pragma unroll
        for (int i = 0; i < 18; ++i) {
            int k = half * 36 + 2 * i;
            w1a[i] = pack2(W1g[k * HH + j0],     W1g[(k + 1) * HH + j0]);
            w1b[i] = pack2(W1g[k * HH + j0 + 1], W1g[(k + 1) * HH + j0 + 1]);
        }
        const float b10 = b1g[j0], b11 = b1g[j0 + 1];

        __syncthreads();               // init complete

        for (int it = 0; it < 196 * 6; ++it) {
#pragma unroll
            for (int G = 0; G < 2; ++G) {
                const int nr = (G == 0) ? G0N : 3;
                BSYNC(1 + G, 512);                 // wait z(G) ready
                const float* zb = zbuf + G * 288 + half * 36;
                float pr0[4], pr1[4];
#pragma unroll
                for (int r = 0; r < 4; ++r) {
                    if (r < nr) {
                        const ulonglong2* zr =
                            reinterpret_cast<const ulonglong2*>(zb + r * ZZ);
                        u64 a0 = 0ull, a1 = 0ull, c0 = 0ull, c1 = 0ull;
#pragma unroll
                        for (int i = 0; i < 9; ++i) {  // 9 LDS.128, 36 FMA2
                            ulonglong2 zz = zr[i];
                            a0 = fma2(zz.x, w1a[2 * i],     a0);
                            a1 = fma2(zz.y, w1a[2 * i + 1], a1);
                            c0 = fma2(zz.x, w1b[2 * i],     c0);
                            c1 = fma2(zz.y, w1b[2 * i + 1], c1);
                        }
                        float2 fa = unpack2(a0), fb = unpack2(a1);
                        float2 fc = unpack2(c0), fd = unpack2(c1);
                        pr0[r] = (fa.x + fa.y) + (fb.x + fb.y);
                        pr1[r] = (fc.x + fc.y) + (fd.x + fd.y);
                    }
                }
                // half-specialized donate/combine: literal rows, no divergence
                if (half == 0) {
                    p1q[2 * 128 + t] = pack2(pr0[2], pr1[2]);
                    if (nr > 3)
                        p1q[3 * 128 + t] = pack2(pr0[3], pr1[3]);
                    BSYNC(5, 256);                 // L1-internal
                    {
                        float2 pp = unpack2(p1q[0 * 128 + t]);
                        hq[G * 512 + 0 * 128 + t] =
                            pack2(fast_tanh(pr0[0] + pp.x + b10),
                                  fast_tanh(pr1[0] + pp.y + b11));
                    }
                    {
                        float2 pp = unpack2(p1q[1 * 128 + t]);
                        hq[G * 512 + 1 * 128 + t] =
                            pack2(fast_tanh(pr0[1] + pp.x + b10),
                                  fast_tanh(pr1[1] + pp.y + b11));
                    }
                } else {
                    p1q[0 * 128 + t] = pack2(pr0[0], pr1[0]);
                    p1q[1 * 128 + t] = pack2(pr0[1], pr1[1]);
                    BSYNC(5, 256);                 // L1-internal
                    {
                        float2 pp = unpack2(p1q[2 * 128 + t]);
                        hq[G * 512 + 2 * 128 + t] =
                            pack2(fast_tanh(pr0[2] + pp.x + b10),
                                  fast_tanh(pr1[2] + pp.y + b11));
                    }
                    if (nr > 3) {
                        float2 pp = unpack2(p1q[3 * 128 + t]);
                        hq[G * 512 + 3 * 128 + t] =
                            pack2(fast_tanh(pr0[3] + pp.x + b10),
                                  fast_tanh(pr1[3] + pp.y + b11));
                    }
                }
                BARV(3 + G, 512);                  // h(G) ready
            }
        }
    } else {
        // ---------------- LAYER-2 WORKERS (warps 8-15) ----------------
        // dot: thread (pg, dp) cols (2dp, 2dp+1), K-slice [pg*32,+32).
        // Owner: row er = pg&3, element edc = (pg>>2)*32 + dp  (lane-stride-1:
        // conflict-free reduce LDS + z STS, coalesced x0/out).
        const int i2 = tid - 256;
        const int pg = i2 >> 5;
        const int dp = i2 & 31;
        const int c0 = 2 * dp;
        const int er  = pg & 3;
        const int edc = ((pg >> 2) << 5) + dp;
        u64 w2a[16], w2b[16];
#pragma unroll
        for (int i = 0; i < 16; ++i) {
            int k = pg * 32 + 2 * i;
            w2a[i] = pack2(W2g[k * DD + c0],     W2g[(k + 1) * DD + c0]);
            w2b[i] = pack2(W2g[k * DD + c0 + 1], W2g[(k + 1) * DD + c0 + 1]);
        }
        const float b2d = b2g[edc];
        float xc[2], kk[2][6];
#pragma unroll
        for (int G = 0; G < 2; ++G) {
            const int nr = (G == 0) ? G0N : 3;
            const bool own = (nr > 3) ? true : (er < 3);
            if (own) {
                int grow = b0 + (G ? G0N : 0) + er;
                xc[G] = x0g[(size_t)grow * DD + edc];
                out[(size_t)grow * (TT * DD) + edc] = xc[G];   // t index 0
            }
        }

        __syncthreads();               // init complete

        // prologue: z for stage 0 of substep 0 (x-part + u-part), both groups
#pragma unroll
        for (int G = 0; G < 2; ++G) {
            const int nr = (G == 0) ? G0N : 3;
            const bool own = (nr > 3) ? true : (er < 3);
            if (own) zbuf[G * 288 + er * ZZ + edc] = xc[G];
            if (i2 < nr * 8)
                u_interp(zbuf + G * 288, tu, ubuf, G ? G0N : 0, i2, te[0]);
            BARV(1 + G, 512);
        }

        for (int m = 0; m < 196; ++m) {
            const int ci = m >> 2, s = m & 3;
            const float tc0 = te[ci];
            const float dtc = te[ci + 1] - tc0;
            const float dt  = dtc * 0.25f;
            const float tsub = tc0 + dtc * ((float)s * 0.25f);
#pragma unroll
            for (int st = 0; st < 6; ++st) {
#pragma unroll
                for (int G = 0; G < 2; ++G) {
                    const int nr = (G == 0) ? G0N : 3;
                    const bool own = (nr > 3) ? true : (er < 3);
                    BSYNC(3 + G, 512);             // wait h(G)
                    float* zG = zbuf + G * 288;

                    // HOISTED u-part of NEXT z(G): safe right after BSYNC(3+G)
                    // (L1 finished reading z(G); ordered for L1's next read by
                    // our later BARV(1+G)). Overlaps the p2 dot.
                    const bool last = (m == 195) && (st == 5);
                    if (i2 < nr * 8 && !last) {
                        const float CSTN[5] = {0.2f, 0.3f, 0.8f,
                                               (float)(8.0/9.0), 1.0f};
                        float tnext = (st < 5)
                            ? tsub + CSTN[st] * dt
                            : ((s < 3) ? tc0 + dtc * ((float)(s + 1) * 0.25f)
                                       : te[ci + 1]);
                        u_interp(zG, tu, ubuf, G ? G0N : 0, i2, tnext);
                    }

                    const float* hb = hbuf + G * 1024 + pg * 32;
                    u64* p2g = p2q + G * 1024;     // double-buffered by group
#pragma unroll
                    for (int r = 0; r < 4; ++r) {
                        if (r < nr) {
                            const ulonglong2* hr =
                                reinterpret_cast<const ulonglong2*>(hb + r * HH);
                            u64 a0 = 0ull, a1 = 0ull, d0 = 0ull, d1 = 0ull;
#pragma unroll
                            for (int i = 0; i < 8; ++i) {  // 8 LDS.128, 32 FMA2
                                ulonglong2 hh = hr[i];
                                a0 = fma2(hh.x, w2a[2 * i],     a0);
                                a1 = fma2(hh.y, w2a[2 * i + 1], a1);
                                d0 = fma2(hh.x, w2b[2 * i],     d0);
                                d1 = fma2(hh.y, w2b[2 * i + 1], d1);
                            }
                            float2 fa = unpack2(a0), fb = unpack2(a1);
                            float2 fc = unpack2(d0), fd = unpack2(d1);
                            p2g[r * 256 + i2] =
                                pack2((fa.x + fa.y) + (fb.x + fb.y),
                                      (fc.x + fc.y) + (fd.x + fd.y));
                        }
                    }
                    BSYNC(6, 256);                 // L2-internal
                    float kv = 0.0f;
                    if (own) {
                        const float* pe =
                            reinterpret_cast<const float*>(p2g) + er * 512 + edc;
                        kv = b2d;
#pragma unroll
                        for (int pgi = 0; pgi < 8; ++pgi) kv += pe[pgi * 64];
                        kk[G][st] = kv;
                    }
                    if (st < 5) {
                        if (own) {
                            float xs;
                            switch (st) {
                            case 0: xs = xc[G] + dt * (A21 * kk[G][0]); break;
                            case 1: xs = xc[G] + dt * (A31 * kk[G][0] + A32 * kk[G][1]); break;
                            case 2: xs = xc[G] + dt * (A41 * kk[G][0] + A42 * kk[G][1]
                                                     + A43 * kk[G][2]); break;
                            case 3: xs = xc[G] + dt * (A51 * kk[G][0] + A52 * kk[G][1]
                                                     + A53 * kk[G][2] + A54 * kk[G][3]); break;
                            default: xs = xc[G] + dt * (A61 * kk[G][0] + A62 * kk[G][1]
                                                      + A63 * kk[G][2] + A64 * kk[G][3]
                                                      + A65 * kk[G][4]); break;
                            }
                            zG[er * ZZ + edc] = xs;
                        }
                        BARV(1 + G, 512);          // z(G) ready
                    } else {
                        if (own) {
                            float xn = xc[G] + dt * (B1 * kk[G][0] + B3 * kk[G][2]
                                                   + B4 * kk[G][3] + B5 * kk[G][4]
                                                   + B6 * kv);
                            xc[G] = xn;
                            if (s == 3)
                                out[(size_t)(b0 + (G ? G0N : 0) + er) * (TT * DD)
                                    + (ci + 1) * DD + edc] = xn;
                            if (!last) zG[er * ZZ + edc] = xn;
                        }
                        if (!last) BARV(1 + G, 512);   // z(G) ready
                    }
                }
            }
        }
    }
}

__global__ void __launch_bounds__(NT, 1)
node_kernel(const float* __restrict__ x0g, const float* __restrict__ te_g,
            const float* __restrict__ tu_g, const float* __restrict__ u_g,
            const float* __restrict__ W1g, const float* __restrict__ b1g,
            const float* __restrict__ W2g, const float* __restrict__ b2g,
            float* __restrict__ out)
{
    extern __shared__ float sm[];
    const int tid = threadIdx.x;
    const int cta = blockIdx.x;
    // 136 CTAs x 7 rows + 12 CTAs x 6 rows = 1024
    const int NR  = (cta < 136) ? 7 : 6;
    const int b0  = (cta < 136) ? cta * 7 : 952 + (cta - 136) * 6;

    // one-time smem loads (common)
    float* te = sm + OFF_TE;
    float* tu = te + 64;
    for (int i = tid; i < TT;  i += NT) te[i] = te_g[i];
    for (int i = tid; i < TUU; i += NT) tu[i] = tu_g[i];
    for (int i = tid; i < NR * TUU * FF; i += NT) {
        int r = i / (TUU * FF);
        int o = i - r * (TUU * FF);
        sm[i] = u_g[(size_t)(b0 + r) * (TUU * FF) + o];
    }

    if (cta < 136)
        run_cta<4>(sm, tid, b0, x0g, W1g, b1g, W2g, b2g, out);
    else
        run_cta<3>(sm, tid, b0, x0g, W1g, b1g, W2g, b2g, out);
}

extern "C" void kernel_launch(void* const* d_in, const int* in_sizes, int n_in,
                              void* d_out, int out_size) {
    const float* x0 = (const float*)d_in[0];
    const float* te = (const float*)d_in[1];
    const float* tu = (const float*)d_in[2];
    const float* ub = (const float*)d_in[3];
    const float* W1 = (const float*)d_in[4];
    const float* b1 = (const float*)d_in[5];
    const float* W2 = (const float*)d_in[6];
    const float* b2 = (const float*)d_in[7];
    float* out = (float*)d_out;

    const int smem_bytes = SMEM_FLOATS * (int)sizeof(float);   // 60416 B
    cudaFuncSetAttribute(node_kernel,
                         cudaFuncAttributeMaxDynamicSharedMemorySize, smem_bytes);
    node_kernel<<<CTAS, NT, smem_bytes>>>(x0, te, tu, ub, W1, b1, W2, b2, out);
}